// round 3
// baseline (speedup 1.0000x reference)
#include <cuda_runtime.h>
#include <math.h>

#define MAXN 50000
#define MAXE 800000
#define DIN 64      // DIN_N == DIN_E == 64
#define DOUT 128    // H*DOUT = 4*32
#define KDIM 192    // 2*DIN_N + DIN_E
#define TE 128      // edges per block tile

// Scratch (device globals — no allocation allowed)
__device__ float g_ht[MAXN * DOUT];      // transformed node feats [N,128]
__device__ float g_a[MAXE * 4];          // attention logits, then exp values [E,4]
__device__ float g_amax[MAXN * 4];       // per-(dst,head) max
__device__ float g_denom[MAXN * 4];      // per-(dst,head) softmax denom
__device__ int   g_cnt[MAXN];            // per-dst edge count
__device__ int   g_off[MAXN + 1];        // CSR offsets
__device__ int   g_cur[MAXN];            // bucket cursors
__device__ int   g_eid[MAXE];            // edge id per CSR slot
__device__ int   g_esrc[MAXE];           // src node per CSR slot

__device__ __forceinline__ void atomicMaxFloat(float* addr, float value) {
    if (value >= 0.0f) atomicMax((int*)addr, __float_as_int(value));
    else               atomicMin((unsigned int*)addr, __float_as_uint(value));
}

__device__ __forceinline__ unsigned long long pack2(float lo, float hi) {
    unsigned long long r;
    asm("mov.b64 %0, {%1, %2};" : "=l"(r) : "f"(lo), "f"(hi));
    return r;
}
__device__ __forceinline__ void unpack2(unsigned long long v, float& lo, float& hi) {
    asm("mov.b64 {%0, %1}, %2;" : "=f"(lo), "=f"(hi) : "l"(v));
}
__device__ __forceinline__ void fma2(unsigned long long& d, unsigned long long a,
                                     unsigned long long b) {
    asm("fma.rn.f32x2 %0, %1, %2, %0;" : "+l"(d) : "l"(a), "l"(b));
}

// ---------------------------------------------------------------------------
// Kernel 0: init amax to -inf, denom to 0, cnt to 0
// ---------------------------------------------------------------------------
__global__ void init_kernel(int N) {
    int stride = gridDim.x * blockDim.x;
    int total_a = N * 4;
    for (int i = blockIdx.x * blockDim.x + threadIdx.x; i < total_a; i += stride) {
        g_amax[i] = -INFINITY;
        g_denom[i] = 0.0f;
    }
    for (int i = blockIdx.x * blockDim.x + threadIdx.x; i < N; i += stride)
        g_cnt[i] = 0;
}

// ---------------------------------------------------------------------------
// CSR build: histogram -> scan -> bucket
// ---------------------------------------------------------------------------
__global__ void hist_kernel(const int* __restrict__ dst, int E) {
    int stride = gridDim.x * blockDim.x;
    for (int e = blockIdx.x * blockDim.x + threadIdx.x; e < E; e += stride)
        atomicAdd(&g_cnt[dst[e]], 1);
}

__global__ void scan_kernel(int N) {
    __shared__ int part[1024];
    int tid = threadIdx.x;
    int per = (N + 1023) / 1024;
    int start = tid * per;
    int stop  = min(start + per, N);
    int sum = 0;
    for (int i = start; i < stop; i++) sum += g_cnt[i];
    part[tid] = sum;
    __syncthreads();
    // Hillis-Steele inclusive scan
    for (int d = 1; d < 1024; d <<= 1) {
        int v = (tid >= d) ? part[tid - d] : 0;
        __syncthreads();
        part[tid] += v;
        __syncthreads();
    }
    int run = part[tid] - sum;   // exclusive offset for this thread's range
    for (int i = start; i < stop; i++) {
        g_off[i] = run;
        g_cur[i] = run;
        run += g_cnt[i];
    }
    if (tid == 1023) g_off[N] = run;
}

__global__ void bucket_kernel(const int* __restrict__ src,
                              const int* __restrict__ dst, int E) {
    int stride = gridDim.x * blockDim.x;
    for (int e = blockIdx.x * blockDim.x + threadIdx.x; e < E; e += stride) {
        int pos = atomicAdd(&g_cur[dst[e]], 1);
        g_eid[pos]  = e;
        g_esrc[pos] = src[e];
    }
}

// ---------------------------------------------------------------------------
// Kernel 1: node transform  g_ht = nfeats @ W_nodes + b_nodes   [N,128]
// ---------------------------------------------------------------------------
__global__ void node_kernel(const float* __restrict__ nfeats,
                            const float* __restrict__ W_nodes,
                            const float* __restrict__ b_nodes,
                            int N) {
    __shared__ float Ws[DIN * DOUT];   // 32 KB
    __shared__ float xs[DIN];
    int tid = threadIdx.x;

    for (int i = tid; i < DIN * DOUT / 4; i += 128)
        ((float4*)Ws)[i] = ((const float4*)W_nodes)[i];
    float b = b_nodes[tid];
    __syncthreads();

    for (int n = blockIdx.x; n < N; n += gridDim.x) {
        if (tid < DIN / 4)
            ((float4*)xs)[tid] = ((const float4*)(nfeats + (size_t)n * DIN))[tid];
        __syncthreads();
        float acc = b;
#pragma unroll
        for (int k = 0; k < DIN; k++)
            acc += xs[k] * Ws[k * DOUT + tid];
        g_ht[(size_t)n * DOUT + tid] = acc;
        __syncthreads();
    }
}

// ---------------------------------------------------------------------------
// Kernel 2: edge GEMM (f32x2 packed) + leaky_relu + attention + segment max
// ---------------------------------------------------------------------------
__global__ __launch_bounds__(512, 1)
void edge_kernel(const float* __restrict__ nfeats,
                 const float* __restrict__ efeats,
                 const int* __restrict__ src,
                 const int* __restrict__ dst,
                 const float* __restrict__ W_edges,
                 const float* __restrict__ b_edges,
                 const float* __restrict__ W_attn,
                 float* __restrict__ f_out,
                 int E) {
    extern __shared__ float sm[];
    float* Ws  = sm;                      // 192*128
    float* St  = Ws + KDIM * DOUT;        // 192*128  (transposed: [k][edge])
    float* bs  = St + KDIM * TE;          // 128
    float* was = bs + DOUT;               // 32
    int*  sidx = (int*)(was + 32);        // 128
    int*  didx = sidx + TE;               // 128

    int tid  = threadIdx.x;
    int lane = tid & 31;
    int warp = tid >> 5;

    for (int i = tid; i < KDIM * DOUT / 4; i += 512)
        ((float4*)Ws)[i] = ((const float4*)W_edges)[i];
    if (tid < DOUT) bs[tid] = b_edges[tid];
    if (tid < 32)
        was[tid] = W_attn[tid * 4] + W_attn[tid * 4 + 1] +
                   W_attn[tid * 4 + 2] + W_attn[tid * 4 + 3];

    int e0 = blockIdx.x * TE;
    if (tid < TE) {
        int e = e0 + tid;
        sidx[tid] = (e < E) ? src[e] : 0;
        didx[tid] = (e < E) ? dst[e] : 0;
    }
    __syncthreads();

    // gather stack rows into TRANSPOSED smem: St[k][le]
    for (int t = warp; t < 192; t += 16) {
        int seg = t >> 2;
        int eg  = t & 3;
        int le  = eg * 32 + lane;
        int e   = e0 + le;
        float4 v;
        if (seg < 16)
            v = ((const float4*)(nfeats + (size_t)sidx[le] * DIN))[seg];
        else if (seg < 32)
            v = (e < E) ? ((const float4*)(efeats + (size_t)e * DIN))[seg - 16]
                        : make_float4(0, 0, 0, 0);
        else
            v = ((const float4*)(nfeats + (size_t)didx[le] * DIN))[seg - 32];
        int k0 = seg * 4;
        St[(k0 + 0) * TE + le] = v.x;
        St[(k0 + 1) * TE + le] = v.y;
        St[(k0 + 2) * TE + le] = v.z;
        St[(k0 + 3) * TE + le] = v.w;
    }
    __syncthreads();

    int c0  = lane * 4;
    int le0 = warp * 8;

    unsigned long long acc[4][4];
#pragma unroll
    for (int p = 0; p < 4; p++)
#pragma unroll
        for (int c = 0; c < 4; c++)
            acc[p][c] = pack2(bs[c0 + c], bs[c0 + c]);

#pragma unroll 2
    for (int k = 0; k < KDIM; k++) {
        float4 w = *reinterpret_cast<const float4*>(Ws + k * DOUT + c0);
        unsigned long long wd[4];
        wd[0] = pack2(w.x, w.x);
        wd[1] = pack2(w.y, w.y);
        wd[2] = pack2(w.z, w.z);
        wd[3] = pack2(w.w, w.w);
        ulonglong2 sA = *reinterpret_cast<const ulonglong2*>(St + k * TE + le0);
        ulonglong2 sB = *reinterpret_cast<const ulonglong2*>(St + k * TE + le0 + 4);
        unsigned long long sp[4] = {sA.x, sA.y, sB.x, sB.y};
#pragma unroll
        for (int p = 0; p < 4; p++) {
#pragma unroll
            for (int c = 0; c < 4; c++)
                fma2(acc[p][c], sp[p], wd[c]);
        }
    }

    int h = lane >> 3;
    float wa0 = was[(lane & 7) * 4 + 0];
    float wa1 = was[(lane & 7) * 4 + 1];
    float wa2 = was[(lane & 7) * 4 + 2];
    float wa3 = was[(lane & 7) * 4 + 3];

#pragma unroll
    for (int p = 0; p < 4; p++) {
        float lo[4], hi[4];
#pragma unroll
        for (int c = 0; c < 4; c++) unpack2(acc[p][c], lo[c], hi[c]);
#pragma unroll
        for (int half = 0; half < 2; half++) {
            float* f = half ? hi : lo;
            float4 fv;
            fv.x = f[0] >= 0.f ? f[0] : 0.01f * f[0];
            fv.y = f[1] >= 0.f ? f[1] : 0.01f * f[1];
            fv.z = f[2] >= 0.f ? f[2] : 0.01f * f[2];
            fv.w = f[3] >= 0.f ? f[3] : 0.01f * f[3];
            int le = le0 + 2 * p + half;
            int e  = e0 + le;
            if (e < E)
                *reinterpret_cast<float4*>(f_out + (size_t)e * DOUT + c0) = fv;

            float part = fv.x * wa0 + fv.y * wa1 + fv.z * wa2 + fv.w * wa3;
            part += __shfl_xor_sync(0xffffffffu, part, 4);
            part += __shfl_xor_sync(0xffffffffu, part, 2);
            part += __shfl_xor_sync(0xffffffffu, part, 1);
            if ((lane & 7) == 0 && e < E) {
                g_a[(size_t)e * 4 + h] = part;
                atomicMaxFloat(&g_amax[(size_t)didx[le] * 4 + h], part);
            }
        }
    }
}

// ---------------------------------------------------------------------------
// Kernel 3: exp(a - amax[dst]) and segment-sum denom
// ---------------------------------------------------------------------------
__global__ void softmax_kernel(const int* __restrict__ dst, int E) {
    int stride = gridDim.x * blockDim.x;
    int total = E * 4;
    for (int i = blockIdx.x * blockDim.x + threadIdx.x; i < total; i += stride) {
        int e = i >> 2;
        int h = i & 3;
        int d = dst[e];
        float v = expf(g_a[i] - g_amax[d * 4 + h]);
        g_a[i] = v;
        atomicAdd(&g_denom[d * 4 + h], v);
    }
}

// ---------------------------------------------------------------------------
// Kernel 4: CSR aggregation — one warp per dst node, register accumulation,
// single non-atomic store. Also covers zero-init of h_out (writes all nodes).
// ---------------------------------------------------------------------------
__global__ void aggregate_kernel(float* __restrict__ h_out, int N) {
    int n = (blockIdx.x * blockDim.x + threadIdx.x) >> 5;
    int lane = threadIdx.x & 31;
    if (n >= N) return;
    int beg = g_off[n];
    int end = g_off[n + 1];
    int h = lane >> 3;
    float inv_d = (end > beg) ? __frcp_rn(g_denom[(size_t)n * 4 + h]) : 0.0f;
    float4 acc = make_float4(0.f, 0.f, 0.f, 0.f);
    for (int i = beg; i < end; i++) {
        int e = g_eid[i];
        int s = g_esrc[i];
        float w = g_a[(size_t)e * 4 + h] * inv_d;
        float4 ht = *reinterpret_cast<const float4*>(g_ht + (size_t)s * DOUT + lane * 4);
        acc.x += w * ht.x;
        acc.y += w * ht.y;
        acc.z += w * ht.z;
        acc.w += w * ht.w;
    }
    *reinterpret_cast<float4*>(h_out + (size_t)n * DOUT + lane * 4) = acc;
}

// ---------------------------------------------------------------------------
extern "C" void kernel_launch(void* const* d_in, const int* in_sizes, int n_in,
                              void* d_out, int out_size) {
    const float* nfeats  = (const float*)d_in[0];
    const float* efeats  = (const float*)d_in[1];
    const int*   src     = (const int*)d_in[2];
    const int*   dst     = (const int*)d_in[3];
    const float* W_nodes = (const float*)d_in[4];
    const float* b_nodes = (const float*)d_in[5];
    const float* W_edges = (const float*)d_in[6];
    const float* b_edges = (const float*)d_in[7];
    const float* W_attn  = (const float*)d_in[8];

    int N = in_sizes[0] / DIN;
    int E = in_sizes[2];

    float* h_out = (float*)d_out;                      // [N, 4, 32]
    float* f_out = (float*)d_out + (size_t)N * DOUT;   // [E, 4, 32]

    size_t edge_smem = (size_t)(KDIM * DOUT + KDIM * TE + DOUT + 32) * sizeof(float)
                     + 2 * TE * sizeof(int);
    cudaFuncSetAttribute(edge_kernel, cudaFuncAttributeMaxDynamicSharedMemorySize,
                         (int)edge_smem);

    init_kernel<<<256, 256>>>(N);
    hist_kernel<<<512, 256>>>(dst, E);
    scan_kernel<<<1, 1024>>>(N);
    bucket_kernel<<<512, 256>>>(src, dst, E);
    node_kernel<<<1024, 128>>>(nfeats, W_nodes, b_nodes, N);
    int eblocks = (E + TE - 1) / TE;
    edge_kernel<<<eblocks, 512, edge_smem>>>(nfeats, efeats, src, dst,
                                             W_edges, b_edges, W_attn, f_out, E);
    softmax_kernel<<<1024, 256>>>(dst, E);
    aggregate_kernel<<<(N * 32 + 255) / 256, 256>>>(h_out, N);
}